// round 13
// baseline (speedup 1.0000x reference)
#include <cuda_runtime.h>
#include <cuda_bf16.h>

#define FULLMASK 0xFFFFFFFFu

// ---------------- problem constants ----------------
namespace {
constexpr int CELLS0 = 16 * 80 * 80;     // 102400 cells, scale 0
constexpr int CELLS1 = 16 * 40 * 40;     // 25600
constexpr int CELLS2 = 16 * 20 * 20;     // 6400
constexpr int TOTCELLS = CELLS0 + CELLS1 + CELLS2;     // 134400
constexpr int NTARGETS = 2048;
constexpr int OBJ0 = CELLS0 * 3;         // 307200
constexpr int OBJ1 = CELLS1 * 3;         // 76800
constexpr int OBJ2 = CELLS2 * 3;         // 19200
constexpr int OBJTOT = OBJ0 + OBJ1 + OBJ2;             // 403200
constexpr int NSLOT = 64;
// dense: 256 elements per block (1 per thread) -> 1575 blocks, all full.
// Scale boundaries: block 1200 (OBJ0/256) and 1500 ((OBJ0+OBJ1)/256) — exact.
constexpr int DENSE_BLOCKS = OBJTOT / 256;               // 1575
constexpr int DBE0 = OBJ0 / 256;                          // 1200
constexpr int DBE1 = (OBJ0 + OBJ1) / 256;                 // 1500
constexpr int SCATTER_BLOCKS = 24;       // 24*256 = 6144 = 3*2048
constexpr int SPARSE_BLOCKS = 3 * NTARGETS / 8;          // 768
constexpr int DENSE_BASE = SCATTER_BLOCKS;                 // 24
constexpr int SPARSE_BASE = SCATTER_BLOCKS + DENSE_BLOCKS; // 1599
constexpr int TOTAL_BLOCKS = SPARSE_BASE + SPARSE_BLOCKS;  // 2367
}

// ------- static scratch (zero-init; kernel leaves everything clean) ---------
__device__ int      g_win[TOTCELLS];         // winner+1 (0 = empty); sparse cleans
__device__ unsigned g_cmask[TOTCELLS * 3];   // class bitmask; sparse cleans
__device__ double   g_part[3 * 4 * NSLOT];   // [scale][metric][slot]; finalize resets
__device__ unsigned g_scat;                  // scatter-done count (24); finalize resets
__device__ unsigned g_done;                  // block done-counter; finalize resets

// softplus(x) = max(x,0) + log(1 + exp(-|x|));  bce(x,t) = softplus(x) - t*x
__device__ __forceinline__ float sp_factor(float x) {   // (1 + e^-|x|) in (1,2]
    return 1.f + __expf(-fabsf(x));
}

__global__ void __launch_bounds__(256) k_all(const float* __restrict__ p0,
                                             const float* __restrict__ p1,
                                             const float* __restrict__ p2,
                                             const float* __restrict__ tg,
                                             float* __restrict__ out) {
    __shared__ float  red[8][4];
    __shared__ double fsh[12 * NSLOT];
    __shared__ double fr[12];
    __shared__ bool   lastB;

    const int lane = threadIdx.x & 31;
    const int wid = threadIdx.x >> 5;
    const unsigned bid = blockIdx.x;

    if (bid < SCATTER_BLOCKS) {
        // ================= scatter targets into g_win / g_cmask =============
        int tid = bid * 256 + threadIdx.x;               // [0, 6144)
        int s = tid / NTARGETS;
        int j = tid - s * NTARGETS;
        const float* t = tg + j * 6;
        int b = (int)t[0];
        int c = (int)t[1];
        float bx = fminf(fmaxf(t[2], 0.f), 1.f);
        float by = fminf(fmaxf(t[3], 0.f), 1.f);
        int H, W, base;
        if (s == 0)      { H = 80; W = 80; base = 0; }
        else if (s == 1) { H = 40; W = 40; base = CELLS0; }
        else             { H = 20; W = 20; base = CELLS0 + CELLS1; }
        int gx = min(max((int)(bx * (float)W), 0), W - 1);
        int gy = min(max((int)(by * (float)H), 0), H - 1);
        int cell = base + (b * H + gy) * W + gx;
        atomicMax(&g_win[cell], j + 1);                  // last-write-wins == max j
        atomicOr(&g_cmask[cell * 3 + (c >> 5)], 1u << (c & 31));
        __syncthreads();
        if (threadIdx.x == 0) {
            __threadfence();                             // publish scatter results
            atomicAdd(&g_scat, 1u);                      // sparse waits on ==24
        }
    } else if (bid < SPARSE_BASE) {
        // ========== dense objectness: 1 element/thread (R3's 4.28 TB/s shape)
        int bi = bid - DENSE_BASE;                       // [0, 1575)
        int s;
        const float* pred;
        int e;                                           // local element index
        if (bi < DBE0)      { s = 0; pred = p0; e = bi * 256; }
        else if (bi < DBE1) { s = 1; pred = p1; e = bi * 256 - OBJ0; }
        else                { s = 2; pred = p2; e = bi * 256 - OBJ0 - OBJ1; }
        e += threadIdx.x;

        float x = __ldg(pred + (long)e * 85 + 4);
        float acc = fmaxf(x, 0.f) + __logf(sp_factor(x));

        for (int off = 16; off; off >>= 1) acc += __shfl_down_sync(FULLMASK, acc, off);
        if (lane == 0) red[wid][0] = acc;
        __syncthreads();
        if (threadIdx.x == 0) {
            float a = red[0][0] + red[1][0] + red[2][0] + red[3][0]
                    + red[4][0] + red[5][0] + red[6][0] + red[7][0];
            atomicAdd(&g_part[(s * 4 + 0) * NSLOT + (bi & (NSLOT - 1))], (double)a);
        }
    } else {
        // ================= sparse: wait for scatter, then winner math =======
        // Safe: scatter blocks are bids 0..23 -> guaranteed wave-1 residents.
        if (threadIdx.x == 0) {
            while (*(volatile unsigned*)&g_scat != SCATTER_BLOCKS) __nanosleep(64);
            __threadfence();                             // acquire scatter writes
        }
        __syncthreads();

        int sb = bid - SPARSE_BASE;                      // [0, 768)
        int gw = sb * 8 + wid;                           // [0, 6144)
        int s = gw / NTARGETS;
        int j = gw - s * NTARGETS;

        const float* t = tg + j * 6;
        int b = (int)t[0];
        float bx = fminf(fmaxf(t[2], 0.f), 1.f);
        float by = fminf(fmaxf(t[3], 0.f), 1.f);
        int H, W, base;
        const float* pred;
        if (s == 0)      { H = 80; W = 80; base = 0;               pred = p0; }
        else if (s == 1) { H = 40; W = 40; base = CELLS0;          pred = p1; }
        else             { H = 20; W = 20; base = CELLS0 + CELLS1; pred = p2; }
        int gx = min(max((int)(bx * (float)W), 0), W - 1);
        int gy = min(max((int)(by * (float)H), 0), H - 1);
        int cell = base + (b * H + gy) * W + gx;

        bool win = (g_win[cell] == j + 1);

        float objp = 0.f, boxp = 0.f, clsp = 0.f, cntp = 0.f;
        if (win) {
            int rem = gy * W + gx;
            const float* row = pred + ((long)(b * 3) * (H * W) + rem) * 85;
            float v0 = row[lane];
            float v1 = row[lane + 32];
            float v2 = (lane < 21) ? row[lane + 64] : 0.f;

            unsigned m0 = g_cmask[cell * 3 + 0];
            unsigned m1 = g_cmask[cell * 3 + 1];
            unsigned m2 = g_cmask[cell * 3 + 2];
            __syncwarp();
            if (lane == 0) {                             // self-clean for replay
                g_win[cell] = 0;
                g_cmask[cell * 3 + 0] = 0u;
                g_cmask[cell * 3 + 1] = 0u;
                g_cmask[cell * 3 + 2] = 0u;
            }

            // cls channels 5..84: bce(x,t) = max(x,0)+log1p(e^-|x|) - t*x
            float p = 1.f, sm = 0.f, sub = 0.f;
            if (lane >= 5) {
                p *= sp_factor(v0);
                sm += fmaxf(v0, 0.f);
                if ((m0 >> (lane - 5)) & 1u) sub += v0;
            }
            {
                int k = lane + 27;
                unsigned wd = (k < 32) ? m0 : m1;
                p *= sp_factor(v1);
                sm += fmaxf(v1, 0.f);
                if ((wd >> (k & 31)) & 1u) sub += v1;
            }
            if (lane < 21) {
                int k = lane + 59;
                unsigned wd = (k < 64) ? m1 : m2;
                p *= sp_factor(v2);
                sm += fmaxf(v2, 0.f);
                if ((wd >> (k & 31)) & 1u) sub += v2;
            }
            clsp = sm + __logf(p) - sub;                 // 1 LG2 per lane

            if (lane == 4) objp = -v0;                   // bce(x,1)-bce(x,0) = -x

            float px = __shfl_sync(FULLMASK, v0, 0);
            float py = __shfl_sync(FULLMASK, v0, 1);
            float pw = __shfl_sync(FULLMASK, v0, 2);
            float ph = __shfl_sync(FULLMASK, v0, 3);
            if (lane == 0) {
                float tx = bx, ty = by;
                float tw = fminf(fmaxf(t[4], 0.f), 1.f);
                float th = fminf(fmaxf(t[5], 0.f), 1.f);
                float px1 = px - pw * 0.5f, py1 = py - ph * 0.5f;
                float px2 = px + pw * 0.5f, py2 = py + ph * 0.5f;
                float tx1 = tx - tw * 0.5f, ty1 = ty - th * 0.5f;
                float tx2 = tx + tw * 0.5f, ty2 = ty + th * 0.5f;
                float iw = fmaxf(fminf(px2, tx2) - fmaxf(px1, tx1), 0.f);
                float ih = fmaxf(fminf(py2, ty2) - fmaxf(py1, ty1), 0.f);
                float inter = iw * ih;
                float uni = pw * ph + tw * th - inter;
                float iou = inter / (uni + 1e-7f);
                float dx = px - tx, dy = py - ty;
                float cd = dx * dx + dy * dy;
                float ew = fmaxf(px2, tx2) - fminf(px1, tx1);
                float eh = fmaxf(py2, ty2) - fminf(py1, ty1);
                float ed = ew * ew + eh * eh + 1e-7f;
                float dv = atanf(tw / th) - atanf(pw / ph);
                float v = 0.4052847345693511f * dv * dv; // 4/pi^2
                float alpha = v / (1.f - iou + v + 1e-7f);
                boxp = iou - cd / ed - alpha * v;
                cntp = 1.f;
            }
        }

        for (int off = 16; off; off >>= 1) {
            objp += __shfl_down_sync(FULLMASK, objp, off);
            boxp += __shfl_down_sync(FULLMASK, boxp, off);
            clsp += __shfl_down_sync(FULLMASK, clsp, off);
            cntp += __shfl_down_sync(FULLMASK, cntp, off);
        }
        if (lane == 0) {
            red[wid][0] = objp;
            red[wid][1] = boxp;
            red[wid][2] = clsp;
            red[wid][3] = cntp;
        }
        __syncthreads();
        if (threadIdx.x == 0) {
            float o = 0.f, bo = 0.f, c = 0.f, n = 0.f;
            #pragma unroll
            for (int k = 0; k < 8; k++) {
                o += red[k][0]; bo += red[k][1]; c += red[k][2]; n += red[k][3];
            }
            int slot = sb & (NSLOT - 1);
            atomicAdd(&g_part[(s * 4 + 0) * NSLOT + slot], (double)o);
            atomicAdd(&g_part[(s * 4 + 1) * NSLOT + slot], (double)bo);
            atomicAdd(&g_part[(s * 4 + 2) * NSLOT + slot], (double)c);
            atomicAdd(&g_part[(s * 4 + 3) * NSLOT + slot], (double)n);
        }
    }

    // ================= done-counter; last of all 2367 blocks finalizes =======
    __syncthreads();
    if (threadIdx.x == 0) {
        __threadfence();                                 // publish g_part adds
        unsigned prev = atomicAdd(&g_done, 1u);
        lastB = (prev == TOTAL_BLOCKS - 1);
    }
    __syncthreads();
    if (!lastB) return;

    if (threadIdx.x == 0) { g_done = 0u; g_scat = 0u; }  // reset for next replay
    for (int i = threadIdx.x; i < 12 * NSLOT; i += 256) {
        fsh[i] = __ldcg(&g_part[i]);                     // L2 read (atomics in L2)
        g_part[i] = 0.0;                                 // reset for next replay
    }
    __syncthreads();
    if (threadIdx.x < 12) {
        double a = 0.0;
        #pragma unroll
        for (int k = 0; k < NSLOT; k++) a += fsh[threadIdx.x * NSLOT + k];
        fr[threadIdx.x] = a;
    }
    __syncthreads();
    if (threadIdx.x == 0) {
        const double denom[3] = {16.0 * 3 * 80 * 80, 16.0 * 3 * 40 * 40, 16.0 * 3 * 20 * 20};
        double tb = 0.0, to = 0.0, tc = 0.0;
        for (int sc = 0; sc < 3; sc++) {
            double obj = fr[sc * 4 + 0];
            double box = fr[sc * 4 + 1];
            double cls = fr[sc * 4 + 2];
            double cnt = fr[sc * 4 + 3];
            double n = fmax(cnt, 1.0);
            tb += 1.0 - box / n;
            to += obj / denom[sc];
            tc += cls / (n * 80.0);
        }
        double tot = 7.5 * tb + 1.0 * to + 0.5 * tc;
        out[0] = (float)tot;
        out[1] = (float)tb;
        out[2] = (float)to;
        out[3] = (float)tc;
    }
}

// ---------------- launch ----------------
extern "C" void kernel_launch(void* const* d_in, const int* in_sizes, int n_in,
                              void* d_out, int out_size) {
    const float* p0 = (const float*)d_in[0];
    const float* p1 = (const float*)d_in[1];
    const float* p2 = (const float*)d_in[2];
    const float* tg = (const float*)d_in[3];
    float* out = (float*)d_out;

    k_all<<<TOTAL_BLOCKS, 256>>>(p0, p1, p2, tg, out);
}

// round 15
// speedup vs baseline: 1.1425x; 1.1425x over previous
#include <cuda_runtime.h>
#include <cuda_bf16.h>

#define FULLMASK 0xFFFFFFFFu

// ---------------- problem constants ----------------
namespace {
constexpr int CELLS0 = 16 * 80 * 80;     // 102400 cells, scale 0
constexpr int CELLS1 = 16 * 40 * 40;     // 25600
constexpr int CELLS2 = 16 * 20 * 20;     // 6400
constexpr int TOTCELLS = CELLS0 + CELLS1 + CELLS2;     // 134400
constexpr int NTARGETS = 2048;
constexpr int OBJ2 = CELLS2 * 3;         // 19200
constexpr int NSLOT = 64;
constexpr int DB0 = 300;                 // dense blocks (1024 el each), scale 0
constexpr int DB1 = 75;
constexpr int DB2 = 19;                  // last partial (19200 = 18*1024 + 768)
constexpr int DENSE_BLOCKS = DB0 + DB1 + DB2;            // 394
constexpr int SCATTER_BLOCKS = 24;       // 24*256 = 6144 = 3*2048
constexpr int SPARSE_BLOCKS = 3 * NTARGETS / 8;          // 768
constexpr int DENSE_BASE = SCATTER_BLOCKS;               // 24
constexpr int SPARSE_BASE = SCATTER_BLOCKS + DENSE_BLOCKS; // 418
constexpr int TOTAL_BLOCKS = SPARSE_BASE + SPARSE_BLOCKS;  // 1186
}

// ------- static scratch (zero-init; kernel leaves everything clean) ---------
__device__ int      g_win[TOTCELLS];         // winner+1 (0 = empty); sparse cleans
__device__ unsigned g_cmask[TOTCELLS * 3];   // class bitmask; sparse cleans
__device__ double   g_part[3 * 4 * NSLOT];   // [scale][metric][slot]; finalize resets
__device__ unsigned g_scat;                  // scatter-done count (24); finalize resets
__device__ unsigned g_done;                  // block done-counter; finalize resets

// softplus(x) = max(x,0) + log(1 + exp(-|x|));  bce(x,t) = softplus(x) - t*x
__device__ __forceinline__ float sp_factor(float x) {   // (1 + e^-|x|) in (1,2]
    return 1.f + __expf(-fabsf(x));
}

// L2 evict-last via createpolicy + cache_hint (scalar-load-legal on sm_100a;
// the inline .L2::evict_last qualifier is 256-bit-only per ptxas).
__device__ __forceinline__ unsigned long long mk_evict_last_policy() {
    unsigned long long pol;
    asm("createpolicy.fractional.L2::evict_last.b64 %0, 1.0;" : "=l"(pol));
    return pol;
}
__device__ __forceinline__ float ldg_el(const float* p, unsigned long long pol) {
    float v;
    asm volatile("ld.global.nc.L2::cache_hint.f32 %0, [%1], %2;"
                 : "=f"(v) : "l"(p), "l"(pol));
    return v;
}

__global__ void __launch_bounds__(256) k_all(const float* __restrict__ p0,
                                             const float* __restrict__ p1,
                                             const float* __restrict__ p2,
                                             const float* __restrict__ tg,
                                             float* __restrict__ out) {
    __shared__ float  red[8][4];
    __shared__ double fsh[12 * NSLOT];
    __shared__ double fr[12];
    __shared__ bool   lastB;

    const int lane = threadIdx.x & 31;
    const int wid = threadIdx.x >> 5;
    const unsigned bid = blockIdx.x;

    if (bid < SCATTER_BLOCKS) {
        // ================= scatter targets into g_win / g_cmask =============
        int tid = bid * 256 + threadIdx.x;               // [0, 6144)
        int s = tid / NTARGETS;
        int j = tid - s * NTARGETS;
        const float* t = tg + j * 6;
        int b = (int)t[0];
        int c = (int)t[1];
        float bx = fminf(fmaxf(t[2], 0.f), 1.f);
        float by = fminf(fmaxf(t[3], 0.f), 1.f);
        int H, W, base;
        if (s == 0)      { H = 80; W = 80; base = 0; }
        else if (s == 1) { H = 40; W = 40; base = CELLS0; }
        else             { H = 20; W = 20; base = CELLS0 + CELLS1; }
        int gx = min(max((int)(bx * (float)W), 0), W - 1);
        int gy = min(max((int)(by * (float)H), 0), H - 1);
        int cell = base + (b * H + gy) * W + gx;
        atomicMax(&g_win[cell], j + 1);                  // last-write-wins == max j
        atomicOr(&g_cmask[cell * 3 + (c >> 5)], 1u << (c & 31));
        __syncthreads();
        if (threadIdx.x == 0) {
            __threadfence();                             // publish scatter results
            atomicAdd(&g_scat, 1u);                      // sparse waits on ==24
        }
    } else if (bid < SPARSE_BASE) {
        // ===== dense objectness, MLP=4, evict-last loads (L2 retention) =====
        int bi = bid - DENSE_BASE;                       // [0, 394)
        int s;
        const float* pred;
        int e0;
        bool full;
        if (bi < DB0)            { s = 0; pred = p0; e0 = bi * 1024;               full = true; }
        else if (bi < DB0 + DB1) { s = 1; pred = p1; e0 = (bi - DB0) * 1024;       full = true; }
        else                     { s = 2; pred = p2; e0 = (bi - DB0 - DB1) * 1024; full = (bi != DENSE_BLOCKS - 1); }

        unsigned long long pol = mk_evict_last_policy();
        int e = e0 + threadIdx.x * 4;
        float acc;
        if (full) {
            float x0 = ldg_el(pred + (long)(e + 0) * 85 + 4, pol);
            float x1 = ldg_el(pred + (long)(e + 1) * 85 + 4, pol);
            float x2 = ldg_el(pred + (long)(e + 2) * 85 + 4, pol);
            float x3 = ldg_el(pred + (long)(e + 3) * 85 + 4, pol);
            float p = sp_factor(x0) * sp_factor(x1) * sp_factor(x2) * sp_factor(x3);
            acc = fmaxf(x0, 0.f) + fmaxf(x1, 0.f) + fmaxf(x2, 0.f) + fmaxf(x3, 0.f)
                + __logf(p);                             // 1 LG2 per 4 elements
        } else {
            float p = 1.f;
            acc = 0.f;
            #pragma unroll
            for (int q = 0; q < 4; q++) {
                if (e + q < OBJ2) {
                    float x = ldg_el(pred + (long)(e + q) * 85 + 4, pol);
                    p *= sp_factor(x);
                    acc += fmaxf(x, 0.f);
                }
            }
            acc += __logf(p);
        }

        for (int off = 16; off; off >>= 1) acc += __shfl_down_sync(FULLMASK, acc, off);
        if (lane == 0) red[wid][0] = acc;
        __syncthreads();
        if (threadIdx.x == 0) {
            float a = red[0][0] + red[1][0] + red[2][0] + red[3][0]
                    + red[4][0] + red[5][0] + red[6][0] + red[7][0];
            atomicAdd(&g_part[(s * 4 + 0) * NSLOT + (bi & (NSLOT - 1))], (double)a);
        }
    } else {
        // ================= sparse: wait for scatter, then winner math =======
        // Safe: scatter blocks are bids 0..23 -> guaranteed wave-1 residents.
        if (threadIdx.x == 0) {
            while (*(volatile unsigned*)&g_scat != SCATTER_BLOCKS) __nanosleep(64);
            __threadfence();                             // acquire scatter writes
        }
        __syncthreads();

        int sb = bid - SPARSE_BASE;                      // [0, 768)
        int gw = sb * 8 + wid;                           // [0, 6144)
        int s = gw / NTARGETS;
        int j = gw - s * NTARGETS;

        const float* t = tg + j * 6;
        int b = (int)t[0];
        float bx = fminf(fmaxf(t[2], 0.f), 1.f);
        float by = fminf(fmaxf(t[3], 0.f), 1.f);
        int H, W, base;
        const float* pred;
        if (s == 0)      { H = 80; W = 80; base = 0;               pred = p0; }
        else if (s == 1) { H = 40; W = 40; base = CELLS0;          pred = p1; }
        else             { H = 20; W = 20; base = CELLS0 + CELLS1; pred = p2; }
        int gx = min(max((int)(bx * (float)W), 0), W - 1);
        int gy = min(max((int)(by * (float)H), 0), H - 1);
        int cell = base + (b * H + gy) * W + gx;

        bool win = (g_win[cell] == j + 1);

        float objp = 0.f, boxp = 0.f, clsp = 0.f, cntp = 0.f;
        if (win) {
            int rem = gy * W + gx;
            const float* row = pred + ((long)(b * 3) * (H * W) + rem) * 85;
            float v0 = row[lane];
            float v1 = row[lane + 32];
            float v2 = (lane < 21) ? row[lane + 64] : 0.f;

            unsigned m0 = g_cmask[cell * 3 + 0];
            unsigned m1 = g_cmask[cell * 3 + 1];
            unsigned m2 = g_cmask[cell * 3 + 2];
            __syncwarp();
            if (lane == 0) {                             // self-clean for replay
                g_win[cell] = 0;
                g_cmask[cell * 3 + 0] = 0u;
                g_cmask[cell * 3 + 1] = 0u;
                g_cmask[cell * 3 + 2] = 0u;
            }

            // cls channels 5..84: bce(x,t) = max(x,0)+log1p(e^-|x|) - t*x
            float p = 1.f, sm = 0.f, sub = 0.f;
            if (lane >= 5) {
                p *= sp_factor(v0);
                sm += fmaxf(v0, 0.f);
                if ((m0 >> (lane - 5)) & 1u) sub += v0;
            }
            {
                int k = lane + 27;
                unsigned wd = (k < 32) ? m0 : m1;
                p *= sp_factor(v1);
                sm += fmaxf(v1, 0.f);
                if ((wd >> (k & 31)) & 1u) sub += v1;
            }
            if (lane < 21) {
                int k = lane + 59;
                unsigned wd = (k < 64) ? m1 : m2;
                p *= sp_factor(v2);
                sm += fmaxf(v2, 0.f);
                if ((wd >> (k & 31)) & 1u) sub += v2;
            }
            clsp = sm + __logf(p) - sub;                 // 1 LG2 per lane

            if (lane == 4) objp = -v0;                   // bce(x,1)-bce(x,0) = -x

            float px = __shfl_sync(FULLMASK, v0, 0);
            float py = __shfl_sync(FULLMASK, v0, 1);
            float pw = __shfl_sync(FULLMASK, v0, 2);
            float ph = __shfl_sync(FULLMASK, v0, 3);
            if (lane == 0) {
                float tx = bx, ty = by;
                float tw = fminf(fmaxf(t[4], 0.f), 1.f);
                float th = fminf(fmaxf(t[5], 0.f), 1.f);
                float px1 = px - pw * 0.5f, py1 = py - ph * 0.5f;
                float px2 = px + pw * 0.5f, py2 = py + ph * 0.5f;
                float tx1 = tx - tw * 0.5f, ty1 = ty - th * 0.5f;
                float tx2 = tx + tw * 0.5f, ty2 = ty + th * 0.5f;
                float iw = fmaxf(fminf(px2, tx2) - fmaxf(px1, tx1), 0.f);
                float ih = fmaxf(fminf(py2, ty2) - fmaxf(py1, ty1), 0.f);
                float inter = iw * ih;
                float uni = pw * ph + tw * th - inter;
                float iou = inter / (uni + 1e-7f);
                float dx = px - tx, dy = py - ty;
                float cd = dx * dx + dy * dy;
                float ew = fmaxf(px2, tx2) - fminf(px1, tx1);
                float eh = fmaxf(py2, ty2) - fminf(py1, ty1);
                float ed = ew * ew + eh * eh + 1e-7f;
                float dv = atanf(tw / th) - atanf(pw / ph);
                float v = 0.4052847345693511f * dv * dv; // 4/pi^2
                float alpha = v / (1.f - iou + v + 1e-7f);
                boxp = iou - cd / ed - alpha * v;
                cntp = 1.f;
            }
        }

        for (int off = 16; off; off >>= 1) {
            objp += __shfl_down_sync(FULLMASK, objp, off);
            boxp += __shfl_down_sync(FULLMASK, boxp, off);
            clsp += __shfl_down_sync(FULLMASK, clsp, off);
            cntp += __shfl_down_sync(FULLMASK, cntp, off);
        }
        if (lane == 0) {
            red[wid][0] = objp;
            red[wid][1] = boxp;
            red[wid][2] = clsp;
            red[wid][3] = cntp;
        }
        __syncthreads();
        if (threadIdx.x == 0) {
            float o = 0.f, bo = 0.f, c = 0.f, n = 0.f;
            #pragma unroll
            for (int k = 0; k < 8; k++) {
                o += red[k][0]; bo += red[k][1]; c += red[k][2]; n += red[k][3];
            }
            int slot = sb & (NSLOT - 1);
            atomicAdd(&g_part[(s * 4 + 0) * NSLOT + slot], (double)o);
            atomicAdd(&g_part[(s * 4 + 1) * NSLOT + slot], (double)bo);
            atomicAdd(&g_part[(s * 4 + 2) * NSLOT + slot], (double)c);
            atomicAdd(&g_part[(s * 4 + 3) * NSLOT + slot], (double)n);
        }
    }

    // ================= done-counter; last of all 1186 blocks finalizes =======
    __syncthreads();
    if (threadIdx.x == 0) {
        __threadfence();                                 // publish g_part adds
        unsigned prev = atomicAdd(&g_done, 1u);
        lastB = (prev == TOTAL_BLOCKS - 1);
    }
    __syncthreads();
    if (!lastB) return;

    if (threadIdx.x == 0) { g_done = 0u; g_scat = 0u; }  // reset for next replay
    for (int i = threadIdx.x; i < 12 * NSLOT; i += 256) {
        fsh[i] = __ldcg(&g_part[i]);                     // L2 read (atomics in L2)
        g_part[i] = 0.0;                                 // reset for next replay
    }
    __syncthreads();
    if (threadIdx.x < 12) {
        double a = 0.0;
        #pragma unroll
        for (int k = 0; k < NSLOT; k++) a += fsh[threadIdx.x * NSLOT + k];
        fr[threadIdx.x] = a;
    }
    __syncthreads();
    if (threadIdx.x == 0) {
        const double denom[3] = {16.0 * 3 * 80 * 80, 16.0 * 3 * 40 * 40, 16.0 * 3 * 20 * 20};
        double tb = 0.0, to = 0.0, tc = 0.0;
        for (int sc = 0; sc < 3; sc++) {
            double obj = fr[sc * 4 + 0];
            double box = fr[sc * 4 + 1];
            double cls = fr[sc * 4 + 2];
            double cnt = fr[sc * 4 + 3];
            double n = fmax(cnt, 1.0);
            tb += 1.0 - box / n;
            to += obj / denom[sc];
            tc += cls / (n * 80.0);
        }
        double tot = 7.5 * tb + 1.0 * to + 0.5 * tc;
        out[0] = (float)tot;
        out[1] = (float)tb;
        out[2] = (float)to;
        out[3] = (float)tc;
    }
}

// ---------------- launch ----------------
extern "C" void kernel_launch(void* const* d_in, const int* in_sizes, int n_in,
                              void* d_out, int out_size) {
    const float* p0 = (const float*)d_in[0];
    const float* p1 = (const float*)d_in[1];
    const float* p2 = (const float*)d_in[2];
    const float* tg = (const float*)d_in[3];
    float* out = (float*)d_out;

    k_all<<<TOTAL_BLOCKS, 256>>>(p0, p1, p2, tg, out);
}